// round 10
// baseline (speedup 1.0000x reference)
#include <cuda_runtime.h>
#include <cstdint>

// Problem constants
#define N_ENS  4
#define N_IN   16384
#define N_OUT  4096
#define CIN    16
#define COUT   16
#define KS     1024                  // K-slab (floats) staged in SMEM per buffer
#define NSLAB  (N_IN / KS)           // 16
#define SLABS_TOTAL (N_ENS * NSLAB)  // 64
#define THREADS 512                  // 16 warps: 8 row-groups x 2 K-halves
#define MAIN_BLOCKS (N_OUT / 32)     // 128
#define NBLW (SLABS_TOTAL * 2)       // per-warp pipeline blocks (2 per slab)

// Scratch: xw planes [n][g2][i] as float2 (pair over g). 4 MB, 16B-aligned.
__device__ float4 g_xwT4[(N_ENS * 8 * N_IN) / 2];

union F2U { float2 f; unsigned long long u; };

__device__ __forceinline__ float2 ffma2(float2 a, float2 b, float2 c) {
    F2U A, B, C, D;
    A.f = a; B.f = b; C.f = c;
    asm("fma.rn.f32x2 %0, %1, %2, %3;"
        : "=l"(D.u) : "l"(A.u), "l"(B.u), "l"(C.u));
    return D.f;
}

__device__ __forceinline__ uint32_t smem_u32(const void* p) {
    uint32_t a;
    asm("{ .reg .u64 t; cvta.to.shared.u64 t, %1; cvt.u32.u64 %0, t; }"
        : "=r"(a) : "l"(p));
    return a;
}

__device__ __forceinline__ void cp_async16(uint32_t saddr, const void* gptr) {
    asm volatile("cp.async.cg.shared.global [%0], [%1], 16;"
                 :: "r"(saddr), "l"(gptr));
}
__device__ __forceinline__ void cp_commit() {
    asm volatile("cp.async.commit_group;");
}

// ---------------------------------------------------------------------------
// Kernel 0: xw[n][i][g] = 0.25 * sum_f x[i][f] * W[n][f][g], plane-major
// float2: g_xwT[(n*8+g2)*N_IN + i].
// ---------------------------------------------------------------------------
__global__ void precompute_xw(const float* __restrict__ x,
                              const float* __restrict__ Ws) {
    __shared__ float sW[CIN * COUT];
    const int n = blockIdx.y;
    sW[threadIdx.x] = Ws[n * (CIN * COUT) + threadIdx.x];
    __syncthreads();

    const int i = blockIdx.x * 256 + threadIdx.x;

    float xf[16];
    const float4* xv = reinterpret_cast<const float4*>(x + (size_t)i * CIN);
#pragma unroll
    for (int q = 0; q < 4; ++q)
        reinterpret_cast<float4*>(xf)[q] = xv[q];

    float y[16];
#pragma unroll
    for (int g = 0; g < 16; ++g) y[g] = 0.f;
#pragma unroll
    for (int f = 0; f < 16; ++f)
#pragma unroll
        for (int g = 0; g < 16; ++g)
            y[g] += xf[f] * sW[f * 16 + g];

    float2* xwT = reinterpret_cast<float2*>(g_xwT4);
#pragma unroll
    for (int g2 = 0; g2 < 8; ++g2)
        xwT[(size_t)(n * 8 + g2) * N_IN + i] =
            make_float2(0.25f * y[2 * g2], 0.25f * y[2 * g2 + 1]);
}

// ---------------------------------------------------------------------------
// Main kernel. 16 warps = 8 row-groups x 2 K-halves; 4 rows/warp; 32 rows/CTA.
// Lane L owns k = {2L, 2L+1} within a 64-k big-iteration:
//   A: per row one LDG.64 (float2), perfectly coalesced 256 B/warp.
//   w: per g2 one LDS.128 at byte offset 16*L -> conflict-free.
// A stream software-pipelined one 256-k block ahead in registers; xw slabs
// cp.async double-buffered in SMEM (each K-half warp reads its half-slab).
// ---------------------------------------------------------------------------
extern __shared__ float2 s_xw[];   // 2 buffers x 8*KS float2 = 128 KB

__global__ __launch_bounds__(THREADS, 1)
void mfgl_main(const float* __restrict__ A,
               const float* __restrict__ bs,
               float* __restrict__ out) {
    const int tid  = threadIdx.x;
    const int lane = tid & 31;
    const int wid  = tid >> 5;
    const int rg   = wid & 7;     // row-group 0..7
    const int kh   = wid >> 3;    // K-half 0..1
    const int row0 = blockIdx.x * 32 + rg * 4;

    const float2* __restrict__ xwT = reinterpret_cast<const float2*>(g_xwT4);
    const uint32_t sbase = smem_u32(s_xw);

    float2 acc[4][8];
#pragma unroll
    for (int r = 0; r < 4; ++r)
#pragma unroll
        for (int g = 0; g < 8; ++g)
            acc[r][g] = make_float2(0.f, 0.f);

    // Per-warp pipeline block blw in [0, NBLW): slab idx = blw>>1, j = blw&1.
    // Covers 256 k at slab offset (kh*2 + j)*256.
    auto a_base = [&](int blw) -> const float2* {
        const int idx = blw >> 1;
        const int j   = blw & 1;
        const int n   = idx >> 4;
        const int k0  = (idx & 15) * KS + (kh * 2 + j) * 256;
        return reinterpret_cast<const float2*>(
            A + ((size_t)(n * N_OUT + row0)) * N_IN + k0) + lane;
    };

    // cp.async one xw slab into buffer BUF. 64 KB = 4096 x 16B chunks,
    // 512 threads x 8 chunks each.
#define PREFETCH_XW(IDX, BUF)                                               \
    do {                                                                    \
        const int _n = (IDX) >> 4;                                          \
        const int _k0 = ((IDX) & 15) * KS;                                  \
        const float2* __restrict__ _xw = xwT + (size_t)_n * 8 * N_IN;       \
        const uint32_t _dst = sbase + (BUF) * 65536u + (uint32_t)tid * 16u; \
        _Pragma("unroll")                                                   \
        for (int _i = 0; _i < 8; ++_i) {                                    \
            const int _c  = tid + _i * THREADS;                             \
            const int _g2 = _c >> 9;            /* 512 chunks per plane */  \
            const int _kk = (_c & 511) << 1;                                \
            cp_async16(_dst + (uint32_t)_i * (THREADS * 16u),               \
                       _xw + (size_t)_g2 * N_IN + _k0 + _kk);               \
        }                                                                   \
        cp_commit();                                                        \
    } while (0)

    PREFETCH_XW(0, 0);

    // Prime A register pipeline with per-warp block 0.
    float2 cur[4][4];
    {
        const float2* pb = a_base(0);
#pragma unroll
        for (int r = 0; r < 4; ++r)
#pragma unroll
            for (int ts = 0; ts < 4; ++ts)
                cur[r][ts] = pb[(size_t)r * (N_IN / 2) + ts * 32];
    }

    for (int idx = 0; idx < SLABS_TOTAL; ++idx) {
        if (idx + 1 < SLABS_TOTAL) {
            PREFETCH_XW(idx + 1, (idx + 1) & 1);
            asm volatile("cp.async.wait_group 1;");   // slab idx complete
        } else {
            asm volatile("cp.async.wait_group 0;");
        }
        __syncthreads();

        const float2* __restrict__ sx = s_xw + (idx & 1) * (8 * KS);

#pragma unroll
        for (int j = 0; j < 2; ++j) {
            // --- prefetch this warp's next 256-k block of A ------------
            float2 nxt[4][4];
            {
                int bln = idx * 2 + j + 1;
                if (bln >= NBLW) bln = 0;   // dead load, in-bounds
                const float2* pb = a_base(bln);
#pragma unroll
                for (int r = 0; r < 4; ++r)
#pragma unroll
                    for (int ts = 0; ts < 4; ++ts)
                        nxt[r][ts] = pb[(size_t)r * (N_IN / 2) + ts * 32];
            }

            // --- compute current block (4 big-iters x 64 k) ------------
#pragma unroll
            for (int ts = 0; ts < 4; ++ts) {
                const int off = ((kh * 2 + j) * 4 + ts) * 64 + 2 * lane;
                const float2 a0 = cur[0][ts];
                const float2 a1 = cur[1][ts];
                const float2 a2 = cur[2][ts];
                const float2 a3 = cur[3][ts];
                const float2 p0x = make_float2(a0.x, a0.x);
                const float2 p0y = make_float2(a0.y, a0.y);
                const float2 p1x = make_float2(a1.x, a1.x);
                const float2 p1y = make_float2(a1.y, a1.y);
                const float2 p2x = make_float2(a2.x, a2.x);
                const float2 p2y = make_float2(a2.y, a2.y);
                const float2 p3x = make_float2(a3.x, a3.x);
                const float2 p3y = make_float2(a3.y, a3.y);
#pragma unroll
                for (int g2 = 0; g2 < 8; ++g2) {
                    const float4 wv = *reinterpret_cast<const float4*>(
                        sx + (size_t)g2 * KS + off);
                    const float2 wk0 = make_float2(wv.x, wv.y);
                    const float2 wk1 = make_float2(wv.z, wv.w);
                    acc[0][g2] = ffma2(p0x, wk0, acc[0][g2]);
                    acc[0][g2] = ffma2(p0y, wk1, acc[0][g2]);
                    acc[1][g2] = ffma2(p1x, wk0, acc[1][g2]);
                    acc[1][g2] = ffma2(p1y, wk1, acc[1][g2]);
                    acc[2][g2] = ffma2(p2x, wk0, acc[2][g2]);
                    acc[2][g2] = ffma2(p2y, wk1, acc[2][g2]);
                    acc[3][g2] = ffma2(p3x, wk0, acc[3][g2]);
                    acc[3][g2] = ffma2(p3y, wk1, acc[3][g2]);
                }
            }

#pragma unroll
            for (int r = 0; r < 4; ++r)
#pragma unroll
                for (int ts = 0; ts < 4; ++ts)
                    cur[r][ts] = nxt[r][ts];
        }
        __syncthreads();   // WAR on smem buffer (idx & 1)
    }

    // Warp-level butterfly reduction across the 32-lane K split.
#pragma unroll
    for (int r = 0; r < 4; ++r)
#pragma unroll
        for (int g = 0; g < 8; ++g) {
            float xx = acc[r][g].x;
            float yy = acc[r][g].y;
#pragma unroll
            for (int off = 16; off > 0; off >>= 1) {
                xx += __shfl_xor_sync(0xffffffffu, xx, off);
                yy += __shfl_xor_sync(0xffffffffu, yy, off);
            }
            acc[r][g] = make_float2(xx, yy);
        }

    // Cross-K-half reduction via SMEM (reuse slab buffer; all compute done).
    float2* s_red = s_xw;   // 8 rg * 4 r * 8 g2 = 256 float2 = 2 KB
    __syncthreads();
    if (kh == 1 && lane == 0) {
#pragma unroll
        for (int r = 0; r < 4; ++r)
#pragma unroll
            for (int g2 = 0; g2 < 8; ++g2)
                s_red[(rg * 4 + r) * 8 + g2] = acc[r][g2];
    }
    __syncthreads();

    if (kh == 0 && lane == 0) {
        float2* out2 = reinterpret_cast<float2*>(out);
#pragma unroll
        for (int r = 0; r < 4; ++r) {
            const int o = row0 + r;
#pragma unroll
            for (int g2 = 0; g2 < 8; ++g2) {
                const int g = 2 * g2;
                const float bx = 0.25f * (bs[g]     + bs[16 + g] +
                                          bs[32 + g] + bs[48 + g]);
                const float by = 0.25f * (bs[g + 1] + bs[16 + g + 1] +
                                          bs[32 + g + 1] + bs[48 + g + 1]);
                const float2 other = s_red[(rg * 4 + r) * 8 + g2];
                out2[(size_t)o * 8 + g2] =
                    make_float2(acc[r][g2].x + other.x + bx,
                                acc[r][g2].y + other.y + by);
            }
        }
    }
}

// ---------------------------------------------------------------------------
// Launch: inputs in metadata order: x, As, Ws, bs. Output fp32 [4096,16].
// ---------------------------------------------------------------------------
extern "C" void kernel_launch(void* const* d_in, const int* in_sizes, int n_in,
                              void* d_out, int out_size) {
    const float* x  = (const float*)d_in[0];
    const float* As = (const float*)d_in[1];
    const float* Ws = (const float*)d_in[2];
    const float* bs = (const float*)d_in[3];
    float* out = (float*)d_out;

    precompute_xw<<<dim3(N_IN / 256, N_ENS), 256>>>(x, Ws);

    const int smem_bytes = 2 * 8 * KS * (int)sizeof(float2);  // 131072
    cudaFuncSetAttribute(mfgl_main,
                         cudaFuncAttributeMaxDynamicSharedMemorySize,
                         smem_bytes);
    mfgl_main<<<MAIN_BLOCKS, THREADS, smem_bytes>>>(As, bs, out);
}

// round 11
// speedup vs baseline: 1.7613x; 1.7613x over previous
#include <cuda_runtime.h>
#include <cstdint>

// Problem constants
#define N_ENS  4
#define N_IN   16384
#define N_OUT  4096
#define CIN    16
#define COUT   16
#define KS     1024                  // K-slab (floats) staged in SMEM per buffer
#define NSLAB  (N_IN / KS)           // 16
#define SLABS_TOTAL (N_ENS * NSLAB)  // 64
#define THREADS 256                  // 8 warps x 4 rows = 32 rows/block
#define MAIN_BLOCKS (N_OUT / 32)     // 128
#define NBLK_TOTAL (SLABS_TOTAL * 4) // 256 A-pipeline blocks (256 k each)

// Scratch: xw planes [n][g2][i] as float2 (pair over g). 4 MB, 16B-aligned.
__device__ float4 g_xwT4[(N_ENS * 8 * N_IN) / 2];

union F2U { float2 f; unsigned long long u; };

__device__ __forceinline__ float2 ffma2(float2 a, float2 b, float2 c) {
    F2U A, B, C, D;
    A.f = a; B.f = b; C.f = c;
    asm("fma.rn.f32x2 %0, %1, %2, %3;"
        : "=l"(D.u) : "l"(A.u), "l"(B.u), "l"(C.u));
    return D.f;
}

__device__ __forceinline__ uint32_t smem_u32(const void* p) {
    uint32_t a;
    asm("{ .reg .u64 t; cvta.to.shared.u64 t, %1; cvt.u32.u64 %0, t; }"
        : "=r"(a) : "l"(p));
    return a;
}

__device__ __forceinline__ void cp_async16(uint32_t saddr, const void* gptr) {
    asm volatile("cp.async.cg.shared.global [%0], [%1], 16;"
                 :: "r"(saddr), "l"(gptr));
}
__device__ __forceinline__ void cp_commit() {
    asm volatile("cp.async.commit_group;");
}

// ---------------------------------------------------------------------------
// Kernel 0: xw[n][i][g] = 0.25 * sum_f x[i][f] * W[n][f][g], plane-major
// float2: g_xwT[(n*8+g2)*N_IN + i].
// ---------------------------------------------------------------------------
__global__ void precompute_xw(const float* __restrict__ x,
                              const float* __restrict__ Ws) {
    __shared__ float sW[CIN * COUT];
    const int n = blockIdx.y;
    sW[threadIdx.x] = Ws[n * (CIN * COUT) + threadIdx.x];
    __syncthreads();

    const int i = blockIdx.x * 256 + threadIdx.x;

    float xf[16];
    const float4* xv = reinterpret_cast<const float4*>(x + (size_t)i * CIN);
#pragma unroll
    for (int q = 0; q < 4; ++q)
        reinterpret_cast<float4*>(xf)[q] = xv[q];

    float y[16];
#pragma unroll
    for (int g = 0; g < 16; ++g) y[g] = 0.f;
#pragma unroll
    for (int f = 0; f < 16; ++f)
#pragma unroll
        for (int g = 0; g < 16; ++g)
            y[g] += xf[f] * sW[f * 16 + g];

    float2* xwT = reinterpret_cast<float2*>(g_xwT4);
#pragma unroll
    for (int g2 = 0; g2 < 8; ++g2)
        xwT[(size_t)(n * 8 + g2) * N_IN + i] =
            make_float2(0.25f * y[2 * g2], 0.25f * y[2 * g2 + 1]);
}

// ---------------------------------------------------------------------------
// Main kernel. 8 warps x 4 rows/warp = 32 rows/block, grid 128.
// Lane L owns k = {2L, 2L+1} within a 64-k big-iteration:
//   A: per row one LDG.64 (float2), perfectly coalesced 256 B/warp.
//   w: per g2 one LDS.128 at byte offset 16*L -> conflict-free.
// A stream pipelined THREE stages deep (cur / nx1 / nx2, each 256 k):
// loads issued 2 blocks (~640 issue-cyc) before consumption -> DRAM latency
// (577 cyc) fully covered even at 2 warps/SMSP. xw slabs cp.async
// double-buffered in SMEM.
// ---------------------------------------------------------------------------
extern __shared__ float2 s_xw[];   // 2 buffers x 8*KS float2 = 128 KB

__global__ __launch_bounds__(THREADS, 1)
void mfgl_main(const float* __restrict__ A,
               const float* __restrict__ bs,
               float* __restrict__ out) {
    const int tid  = threadIdx.x;
    const int lane = tid & 31;
    const int wid  = tid >> 5;
    const int row0 = blockIdx.x * 32 + wid * 4;

    const float2* __restrict__ xwT = reinterpret_cast<const float2*>(g_xwT4);
    const uint32_t sbase = smem_u32(s_xw);

    float2 acc[4][8];
#pragma unroll
    for (int r = 0; r < 4; ++r)
#pragma unroll
        for (int g = 0; g < 8; ++g)
            acc[r][g] = make_float2(0.f, 0.f);

    // A base of pipeline block bl in [0, 256): slab = bl>>2, 256-k chunk bl&3.
    auto a_base = [&](int bl) -> const float2* {
        const int idx = bl >> 2;
        const int n   = idx >> 4;
        const int k0  = (idx & 15) * KS + (bl & 3) * 256;
        return reinterpret_cast<const float2*>(
            A + ((size_t)(n * N_OUT + row0)) * N_IN + k0) + lane;
    };

    // cp.async one xw slab into buffer BUF. 64 KB = 4096 x 16B chunks.
#define PREFETCH_XW(IDX, BUF)                                               \
    do {                                                                    \
        const int _n = (IDX) >> 4;                                          \
        const int _k0 = ((IDX) & 15) * KS;                                  \
        const float2* __restrict__ _xw = xwT + (size_t)_n * 8 * N_IN;       \
        const uint32_t _dst = sbase + (BUF) * 65536u + (uint32_t)tid * 16u; \
        _Pragma("unroll")                                                   \
        for (int _i = 0; _i < 16; ++_i) {                                   \
            const int _c  = tid + _i * THREADS;                             \
            const int _g2 = _c >> 9;            /* 512 chunks per plane */  \
            const int _kk = (_c & 511) << 1;                                \
            cp_async16(_dst + (uint32_t)_i * (THREADS * 16u),               \
                       _xw + (size_t)_g2 * N_IN + _k0 + _kk);               \
        }                                                                   \
        cp_commit();                                                        \
    } while (0)

    PREFETCH_XW(0, 0);

    // Prime 3-stage A register pipeline with blocks 0 and 1.
    float2 cur[4][4], nx1[4][4];
    {
        const float2* p0 = a_base(0);
        const float2* p1 = a_base(1);
#pragma unroll
        for (int r = 0; r < 4; ++r)
#pragma unroll
            for (int ts = 0; ts < 4; ++ts) {
                cur[r][ts] = p0[(size_t)r * (N_IN / 2) + ts * 32];
                nx1[r][ts] = p1[(size_t)r * (N_IN / 2) + ts * 32];
            }
    }

    for (int idx = 0; idx < SLABS_TOTAL; ++idx) {
        if (idx + 1 < SLABS_TOTAL) {
            PREFETCH_XW(idx + 1, (idx + 1) & 1);
            asm volatile("cp.async.wait_group 1;");   // slab idx complete
        } else {
            asm volatile("cp.async.wait_group 0;");
        }
        __syncthreads();

        const float2* __restrict__ sx = s_xw + (idx & 1) * (8 * KS);

#pragma unroll
        for (int tb = 0; tb < 4; ++tb) {
            // --- issue loads for block bl+2 (consumed 2 blocks later) ---
            float2 nx2[4][4];
            {
                int bl2 = idx * 4 + tb + 2;
                if (bl2 >= NBLK_TOTAL) bl2 -= NBLK_TOTAL;  // dead, in-bounds
                const float2* pb = a_base(bl2);
#pragma unroll
                for (int r = 0; r < 4; ++r)
#pragma unroll
                    for (int ts = 0; ts < 4; ++ts)
                        nx2[r][ts] = pb[(size_t)r * (N_IN / 2) + ts * 32];
            }

            // --- compute current block (4 big-iters x 64 k) ------------
#pragma unroll
            for (int ts = 0; ts < 4; ++ts) {
                const int off = (tb * 4 + ts) * 64 + 2 * lane;  // float2 idx
                const float2 a0 = cur[0][ts];
                const float2 a1 = cur[1][ts];
                const float2 a2 = cur[2][ts];
                const float2 a3 = cur[3][ts];
                const float2 p0x = make_float2(a0.x, a0.x);
                const float2 p0y = make_float2(a0.y, a0.y);
                const float2 p1x = make_float2(a1.x, a1.x);
                const float2 p1y = make_float2(a1.y, a1.y);
                const float2 p2x = make_float2(a2.x, a2.x);
                const float2 p2y = make_float2(a2.y, a2.y);
                const float2 p3x = make_float2(a3.x, a3.x);
                const float2 p3y = make_float2(a3.y, a3.y);
#pragma unroll
                for (int g2 = 0; g2 < 8; ++g2) {
                    const float4 wv = *reinterpret_cast<const float4*>(
                        sx + (size_t)g2 * KS + off);
                    const float2 wk0 = make_float2(wv.x, wv.y);
                    const float2 wk1 = make_float2(wv.z, wv.w);
                    acc[0][g2] = ffma2(p0x, wk0, acc[0][g2]);
                    acc[0][g2] = ffma2(p0y, wk1, acc[0][g2]);
                    acc[1][g2] = ffma2(p1x, wk0, acc[1][g2]);
                    acc[1][g2] = ffma2(p1y, wk1, acc[1][g2]);
                    acc[2][g2] = ffma2(p2x, wk0, acc[2][g2]);
                    acc[2][g2] = ffma2(p2y, wk1, acc[2][g2]);
                    acc[3][g2] = ffma2(p3x, wk0, acc[3][g2]);
                    acc[3][g2] = ffma2(p3y, wk1, acc[3][g2]);
                }
            }

            // --- rotate pipeline (register renames under full unroll) ---
#pragma unroll
            for (int r = 0; r < 4; ++r)
#pragma unroll
                for (int ts = 0; ts < 4; ++ts) {
                    cur[r][ts] = nx1[r][ts];
                    nx1[r][ts] = nx2[r][ts];
                }
        }
        __syncthreads();   // WAR on smem buffer (idx & 1)
    }

    // Warp-level butterfly reduction across the 32-lane K split.
#pragma unroll
    for (int r = 0; r < 4; ++r)
#pragma unroll
        for (int g = 0; g < 8; ++g) {
            float xx = acc[r][g].x;
            float yy = acc[r][g].y;
#pragma unroll
            for (int off = 16; off > 0; off >>= 1) {
                xx += __shfl_xor_sync(0xffffffffu, xx, off);
                yy += __shfl_xor_sync(0xffffffffu, yy, off);
            }
            acc[r][g] = make_float2(xx, yy);
        }

    if (lane == 0) {
        float2* out2 = reinterpret_cast<float2*>(out);
#pragma unroll
        for (int r = 0; r < 4; ++r) {
            const int o = row0 + r;
#pragma unroll
            for (int g2 = 0; g2 < 8; ++g2) {
                const int g = 2 * g2;
                const float bx = 0.25f * (bs[g]     + bs[16 + g] +
                                          bs[32 + g] + bs[48 + g]);
                const float by = 0.25f * (bs[g + 1] + bs[16 + g + 1] +
                                          bs[32 + g + 1] + bs[48 + g + 1]);
                out2[(size_t)o * 8 + g2] =
                    make_float2(acc[r][g2].x + bx, acc[r][g2].y + by);
            }
        }
    }
}

// ---------------------------------------------------------------------------
// Launch: inputs in metadata order: x, As, Ws, bs. Output fp32 [4096,16].
// ---------------------------------------------------------------------------
extern "C" void kernel_launch(void* const* d_in, const int* in_sizes, int n_in,
                              void* d_out, int out_size) {
    const float* x  = (const float*)d_in[0];
    const float* As = (const float*)d_in[1];
    const float* Ws = (const float*)d_in[2];
    const float* bs = (const float*)d_in[3];
    float* out = (float*)d_out;

    precompute_xw<<<dim3(N_IN / 256, N_ENS), 256>>>(x, Ws);

    const int smem_bytes = 2 * 8 * KS * (int)sizeof(float2);  // 131072
    cudaFuncSetAttribute(mfgl_main,
                         cudaFuncAttributeMaxDynamicSharedMemorySize,
                         smem_bytes);
    mfgl_main<<<MAIN_BLOCKS, THREADS, smem_bytes>>>(As, bs, out);
}

// round 12
// speedup vs baseline: 1.8558x; 1.0537x over previous
#include <cuda_runtime.h>
#include <cstdint>

// Problem constants
#define N_ENS  4
#define N_IN   16384
#define N_OUT  4096
#define CIN    16
#define COUT   16
#define KS     1024                  // K-slab (floats) staged in SMEM per buffer
#define NSLAB  (N_IN / KS)           // 16
#define SLABS_TOTAL (N_ENS * NSLAB)  // 64
#define THREADS 256                  // 8 warps x 4 rows = 32 rows/block
#define MAIN_BLOCKS (N_OUT / 32)     // 128
#define NBLK_TOTAL (SLABS_TOTAL * 4) // 256 A-pipeline blocks (256 k each)

// Scratch: xw planes [n][g2][i] as float2 (pair over g). 4 MB, 16B-aligned.
__device__ float4 g_xwT4[(N_ENS * 8 * N_IN) / 2];

union F2U { float2 f; unsigned long long u; };

__device__ __forceinline__ float2 ffma2(float2 a, float2 b, float2 c) {
    F2U A, B, C, D;
    A.f = a; B.f = b; C.f = c;
    asm("fma.rn.f32x2 %0, %1, %2, %3;"
        : "=l"(D.u) : "l"(A.u), "l"(B.u), "l"(C.u));
    return D.f;
}

__device__ __forceinline__ uint32_t smem_u32(const void* p) {
    uint32_t a;
    asm("{ .reg .u64 t; cvta.to.shared.u64 t, %1; cvt.u32.u64 %0, t; }"
        : "=r"(a) : "l"(p));
    return a;
}

__device__ __forceinline__ void cp_async16(uint32_t saddr, const void* gptr) {
    asm volatile("cp.async.cg.shared.global [%0], [%1], 16;"
                 :: "r"(saddr), "l"(gptr));
}
__device__ __forceinline__ void cp_commit() {
    asm volatile("cp.async.commit_group;");
}

// ---------------------------------------------------------------------------
// Kernel 0: xw[n][i][g] = 0.25 * sum_f x[i][f] * W[n][f][g], plane-major
// float2: g_xwT[(n*8+g2)*N_IN + i].
// ---------------------------------------------------------------------------
__global__ void precompute_xw(const float* __restrict__ x,
                              const float* __restrict__ Ws) {
    __shared__ float sW[CIN * COUT];
    const int n = blockIdx.y;
    sW[threadIdx.x] = Ws[n * (CIN * COUT) + threadIdx.x];
    __syncthreads();

    const int i = blockIdx.x * 256 + threadIdx.x;

    float xf[16];
    const float4* xv = reinterpret_cast<const float4*>(x + (size_t)i * CIN);
#pragma unroll
    for (int q = 0; q < 4; ++q)
        reinterpret_cast<float4*>(xf)[q] = xv[q];

    float y[16];
#pragma unroll
    for (int g = 0; g < 16; ++g) y[g] = 0.f;
#pragma unroll
    for (int f = 0; f < 16; ++f)
#pragma unroll
        for (int g = 0; g < 16; ++g)
            y[g] += xf[f] * sW[f * 16 + g];

    float2* xwT = reinterpret_cast<float2*>(g_xwT4);
#pragma unroll
    for (int g2 = 0; g2 < 8; ++g2)
        xwT[(size_t)(n * 8 + g2) * N_IN + i] =
            make_float2(0.25f * y[2 * g2], 0.25f * y[2 * g2 + 1]);
}

// ---------------------------------------------------------------------------
// Main kernel. 8 warps x 4 rows/warp = 32 rows/block, grid 128.
// Lane L owns k = {2L, 2L+1} within a 64-k big-iteration:
//   A: per row one LDG.64 (float2), perfectly coalesced 256 B/warp.
//   w: per g2 one LDS.128 at byte offset 16*L -> conflict-free.
// A stream pipelined FOUR stages deep (cur/nx1/nx2 + in-flight nx3, 256 k
// each); stage-3 loads interleaved one row per ts-iter to smooth DRAM issue.
// xw slabs cp.async double-buffered with ONE __syncthreads per slab:
//   wait_group 0 ; sync ; prefetch(idx+1) ; compute(idx)
// The single sync proves both data-visibility for slab idx and WAR safety
// for the buffer prefetch(idx+1) overwrites (read during slab idx-1).
// ---------------------------------------------------------------------------
extern __shared__ float2 s_xw[];   // 2 buffers x 8*KS float2 = 128 KB

__global__ __launch_bounds__(THREADS, 1)
void mfgl_main(const float* __restrict__ A,
               const float* __restrict__ bs,
               float* __restrict__ out) {
    const int tid  = threadIdx.x;
    const int lane = tid & 31;
    const int wid  = tid >> 5;
    const int row0 = blockIdx.x * 32 + wid * 4;

    const float2* __restrict__ xwT = reinterpret_cast<const float2*>(g_xwT4);
    const uint32_t sbase = smem_u32(s_xw);

    float2 acc[4][8];
#pragma unroll
    for (int r = 0; r < 4; ++r)
#pragma unroll
        for (int g = 0; g < 8; ++g)
            acc[r][g] = make_float2(0.f, 0.f);

    // A base of pipeline block bl in [0, 256): slab = bl>>2, 256-k chunk bl&3.
    auto a_base = [&](int bl) -> const float2* {
        const int idx = bl >> 2;
        const int n   = idx >> 4;
        const int k0  = (idx & 15) * KS + (bl & 3) * 256;
        return reinterpret_cast<const float2*>(
            A + ((size_t)(n * N_OUT + row0)) * N_IN + k0) + lane;
    };

    // cp.async one xw slab into buffer BUF. 64 KB = 4096 x 16B chunks.
#define PREFETCH_XW(IDX, BUF)                                               \
    do {                                                                    \
        const int _n = (IDX) >> 4;                                          \
        const int _k0 = ((IDX) & 15) * KS;                                  \
        const float2* __restrict__ _xw = xwT + (size_t)_n * 8 * N_IN;       \
        const uint32_t _dst = sbase + (BUF) * 65536u + (uint32_t)tid * 16u; \
        _Pragma("unroll")                                                   \
        for (int _i = 0; _i < 16; ++_i) {                                   \
            const int _c  = tid + _i * THREADS;                             \
            const int _g2 = _c >> 9;            /* 512 chunks per plane */  \
            const int _kk = (_c & 511) << 1;                                \
            cp_async16(_dst + (uint32_t)_i * (THREADS * 16u),               \
                       _xw + (size_t)_g2 * N_IN + _k0 + _kk);               \
        }                                                                   \
        cp_commit();                                                        \
    } while (0)

    PREFETCH_XW(0, 0);

    // Prime 4-stage A register pipeline with blocks 0, 1, 2.
    float2 cur[4][4], nx1[4][4], nx2[4][4];
    {
        const float2* p0 = a_base(0);
        const float2* p1 = a_base(1);
        const float2* p2 = a_base(2);
#pragma unroll
        for (int r = 0; r < 4; ++r)
#pragma unroll
            for (int ts = 0; ts < 4; ++ts) {
                cur[r][ts] = p0[(size_t)r * (N_IN / 2) + ts * 32];
                nx1[r][ts] = p1[(size_t)r * (N_IN / 2) + ts * 32];
                nx2[r][ts] = p2[(size_t)r * (N_IN / 2) + ts * 32];
            }
    }

    for (int idx = 0; idx < SLABS_TOTAL; ++idx) {
        asm volatile("cp.async.wait_group 0;");  // slab idx data (mine) done
        __syncthreads();                          // everyone's done + WAR safe
        if (idx + 1 < SLABS_TOTAL)
            PREFETCH_XW(idx + 1, (idx + 1) & 1);  // overlaps compute below

        const float2* __restrict__ sx = s_xw + (idx & 1) * (8 * KS);

#pragma unroll
        for (int tb = 0; tb < 4; ++tb) {
            // Stage-3 block: loads interleaved one row per ts-iter below.
            int bl3 = idx * 4 + tb + 3;
            if (bl3 >= NBLK_TOTAL) bl3 -= NBLK_TOTAL;  // dead load, in-bounds
            const float2* __restrict__ pb3 = a_base(bl3);
            float2 nx3[4][4];

#pragma unroll
            for (int ts = 0; ts < 4; ++ts) {
                // --- issue 4 LDG.64 (row `ts` of block bl+3) -----------
#pragma unroll
                for (int q = 0; q < 4; ++q)
                    nx3[ts][q] = pb3[(size_t)ts * (N_IN / 2) + q * 32];

                // --- compute big-iter ts of current block --------------
                const int off = (tb * 4 + ts) * 64 + 2 * lane;  // float2 idx
                const float2 a0 = cur[0][ts];
                const float2 a1 = cur[1][ts];
                const float2 a2 = cur[2][ts];
                const float2 a3 = cur[3][ts];
                const float2 p0x = make_float2(a0.x, a0.x);
                const float2 p0y = make_float2(a0.y, a0.y);
                const float2 p1x = make_float2(a1.x, a1.x);
                const float2 p1y = make_float2(a1.y, a1.y);
                const float2 p2x = make_float2(a2.x, a2.x);
                const float2 p2y = make_float2(a2.y, a2.y);
                const float2 p3x = make_float2(a3.x, a3.x);
                const float2 p3y = make_float2(a3.y, a3.y);
#pragma unroll
                for (int g2 = 0; g2 < 8; ++g2) {
                    const float4 wv = *reinterpret_cast<const float4*>(
                        sx + (size_t)g2 * KS + off);
                    const float2 wk0 = make_float2(wv.x, wv.y);
                    const float2 wk1 = make_float2(wv.z, wv.w);
                    acc[0][g2] = ffma2(p0x, wk0, acc[0][g2]);
                    acc[0][g2] = ffma2(p0y, wk1, acc[0][g2]);
                    acc[1][g2] = ffma2(p1x, wk0, acc[1][g2]);
                    acc[1][g2] = ffma2(p1y, wk1, acc[1][g2]);
                    acc[2][g2] = ffma2(p2x, wk0, acc[2][g2]);
                    acc[2][g2] = ffma2(p2y, wk1, acc[2][g2]);
                    acc[3][g2] = ffma2(p3x, wk0, acc[3][g2]);
                    acc[3][g2] = ffma2(p3y, wk1, acc[3][g2]);
                }
            }

            // --- rotate pipeline (register renames under full unroll) ---
#pragma unroll
            for (int r = 0; r < 4; ++r)
#pragma unroll
                for (int ts = 0; ts < 4; ++ts) {
                    cur[r][ts] = nx1[r][ts];
                    nx1[r][ts] = nx2[r][ts];
                    nx2[r][ts] = nx3[r][ts];
                }
        }
    }

    // Warp-level butterfly reduction across the 32-lane K split.
#pragma unroll
    for (int r = 0; r < 4; ++r)
#pragma unroll
        for (int g = 0; g < 8; ++g) {
            float xx = acc[r][g].x;
            float yy = acc[r][g].y;
#pragma unroll
            for (int off = 16; off > 0; off >>= 1) {
                xx += __shfl_xor_sync(0xffffffffu, xx, off);
                yy += __shfl_xor_sync(0xffffffffu, yy, off);
            }
            acc[r][g] = make_float2(xx, yy);
        }

    if (lane == 0) {
        float2* out2 = reinterpret_cast<float2*>(out);
#pragma unroll
        for (int r = 0; r < 4; ++r) {
            const int o = row0 + r;
#pragma unroll
            for (int g2 = 0; g2 < 8; ++g2) {
                const int g = 2 * g2;
                const float bx = 0.25f * (bs[g]     + bs[16 + g] +
                                          bs[32 + g] + bs[48 + g]);
                const float by = 0.25f * (bs[g + 1] + bs[16 + g + 1] +
                                          bs[32 + g + 1] + bs[48 + g + 1]);
                out2[(size_t)o * 8 + g2] =
                    make_float2(acc[r][g2].x + bx, acc[r][g2].y + by);
            }
        }
    }
}

// ---------------------------------------------------------------------------
// Launch: inputs in metadata order: x, As, Ws, bs. Output fp32 [4096,16].
// ---------------------------------------------------------------------------
extern "C" void kernel_launch(void* const* d_in, const int* in_sizes, int n_in,
                              void* d_out, int out_size) {
    const float* x  = (const float*)d_in[0];
    const float* As = (const float*)d_in[1];
    const float* Ws = (const float*)d_in[2];
    const float* bs = (const float*)d_in[3];
    float* out = (float*)d_out;

    precompute_xw<<<dim3(N_IN / 256, N_ENS), 256>>>(x, Ws);

    const int smem_bytes = 2 * 8 * KS * (int)sizeof(float2);  // 131072
    cudaFuncSetAttribute(mfgl_main,
                         cudaFuncAttributeMaxDynamicSharedMemorySize,
                         smem_bytes);
    mfgl_main<<<MAIN_BLOCKS, THREADS, smem_bytes>>>(As, bs, out);
}